// round 12
// baseline (speedup 1.0000x reference)
#include <cuda_runtime.h>

// S=64, B=128, D=10000 fixed by the reference.
#define D_DIM   10000
#define D4      2500
#define J_FULL  78            // 78*32 = 2496 float4; tail = 4 (lane<4); 78 = 3*26
#define S_DIM   64
#define B_DIM   128
#define THREADS 512
#define NWARPS  16
#define DEPTH   3
#define SMEM_BYTES (2 * D_DIM * sizeof(float))   // 80000 B

#define L2E 1.4426950408889634f

__device__ float    g_partial[B_DIM];
__device__ unsigned g_ticket;      // zero-init; reset by last CTA each launch

__device__ __forceinline__ float ex2f(float x) {
    float r;
    asm("ex2.approx.ftz.f32 %0, %1;" : "=f"(r) : "f"(x));
    return r;
}

// consume one quad (noise n, theta*log2e t, y yv) into one sample's accumulators
__device__ __forceinline__ void consume1(const float4& n, const float4& t,
                                         const float4& yv,
                                         float& sq, float& sq2, float& sqy)
{
    float qx = ex2f(fmaf(n.x, L2E, t.x));
    float qy = ex2f(fmaf(n.y, L2E, t.y));
    float qz = ex2f(fmaf(n.z, L2E, t.z));
    float qw = ex2f(fmaf(n.w, L2E, t.w));
    sq  += (qx + qy) + (qz + qw);
    sq2 = fmaf(qx, qx, sq2);   sq2 = fmaf(qy, qy, sq2);
    sq2 = fmaf(qz, qz, sq2);   sq2 = fmaf(qw, qw, sq2);
    sqy = fmaf(qx, yv.x, sqy); sqy = fmaf(qy, yv.y, sqy);
    sqy = fmaf(qz, yv.z, sqy); sqy = fmaf(qw, yv.w, sqy);
}

__global__ __launch_bounds__(THREADS, 1)   // 1 CTA/SM -> up to 128 regs/thread
void pl_fused(const float* __restrict__ theta,
              const float* __restrict__ y,
              const float* __restrict__ noise,
              float* __restrict__ out)
{
    extern __shared__ float sm[];          // [0,10000): theta_b*log2e  [10000,20000): y_b
    float* __restrict__ sth = sm;
    float* __restrict__ syy = sm + D_DIM;
    __shared__ float fin[NWARPS];
    __shared__ float s_sy2;
    __shared__ int   is_last;

    const int b    = blockIdx.x;
    const int tid  = threadIdx.x;
    const int lane = tid & 31;
    const int warp = tid >> 5;

    // ---- stage theta_b*log2e, y_b into shared; exact fp32 Sigma(y^2) ----
    float sy2p = 0.0f;
    {
        const float4* __restrict__ th4 = (const float4*)(theta + (size_t)b * D_DIM);
        const float4* __restrict__ yy4 = (const float4*)(y     + (size_t)b * D_DIM);
        float4* s_t = (float4*)sth;
        float4* s_y = (float4*)syy;
        for (int i = tid; i < D4; i += THREADS) {
            float4 t = __ldg(th4 + i);
            float4 v = __ldg(yy4 + i);
            sy2p = fmaf(v.x, v.x, sy2p);
            sy2p = fmaf(v.y, v.y, sy2p);
            sy2p = fmaf(v.z, v.z, sy2p);
            sy2p = fmaf(v.w, v.w, sy2p);
            t.x *= L2E; t.y *= L2E; t.z *= L2E; t.w *= L2E;
            s_t[i] = t;
            s_y[i] = v;
        }
    }
    #pragma unroll
    for (int o = 16; o; o >>= 1) sy2p += __shfl_xor_sync(0xffffffffu, sy2p, o);
    if (lane == 0) fin[warp] = sy2p;
    __syncthreads();
    if (tid == 0) {
        float t = fin[0];
        #pragma unroll
        for (int w = 1; w < NWARPS; w++) t += fin[w];
        s_sy2 = t;
    }
    __syncthreads();
    const float sy2 = s_sy2;

    const float4* __restrict__ st4 = (const float4*)sth;
    const float4* __restrict__ sy4 = (const float4*)syy;

    // ---- single pass: warp owns samples 4*warp .. 4*warp+3 ----
    const size_t rowstride = (size_t)B_DIM * D4;   // float4 stride between samples
    const float4* __restrict__ nz0 =
        (const float4*)(noise + ((size_t)(4 * warp) * B_DIM + b) * D_DIM);
    const float4* __restrict__ nz1 = nz0 + rowstride;
    const float4* __restrict__ nz2 = nz1 + rowstride;
    const float4* __restrict__ nz3 = nz2 + rowstride;

    float q0 = 0.f, q0s = 0.f, q0y = 0.f;
    float q1 = 0.f, q1s = 0.f, q1y = 0.f;
    float q2 = 0.f, q2s = 0.f, q2y = 0.f;
    float q3 = 0.f, q3s = 0.f, q3y = 0.f;

    // rotating depth-3 pipeline per sample (12 live buffers)
    float4 P0[DEPTH], P1[DEPTH], P2[DEPTH], P3[DEPTH];
    #pragma unroll
    for (int k = 0; k < DEPTH; k++) {
        P0[k] = __ldcs(nz0 + k * 32 + lane);
        P1[k] = __ldcs(nz1 + k * 32 + lane);
        P2[k] = __ldcs(nz2 + k * 32 + lane);
        P3[k] = __ldcs(nz3 + k * 32 + lane);
    }

    // 25 blocks: consume j=jj..jj+2, reload j+3 (last reload = 75,76,77)
    #pragma unroll 1
    for (int jj = 0; jj <= 72; jj += 3) {
        #pragma unroll
        for (int k = 0; k < DEPTH; k++) {
            const int idx = (jj + k) * 32 + lane;
            float4 t = st4[idx], yv = sy4[idx];
            consume1(P0[k], t, yv, q0, q0s, q0y);
            consume1(P1[k], t, yv, q1, q1s, q1y);
            consume1(P2[k], t, yv, q2, q2s, q2y);
            consume1(P3[k], t, yv, q3, q3s, q3y);
            P0[k] = __ldcs(nz0 + idx + DEPTH * 32);
            P1[k] = __ldcs(nz1 + idx + DEPTH * 32);
            P2[k] = __ldcs(nz2 + idx + DEPTH * 32);
            P3[k] = __ldcs(nz3 + idx + DEPTH * 32);
        }
    }

    // tail loads (lane<4): quad index 2496..2499, issued before epilogue
    float4 t0, t1, t2, t3;
    if (lane < 4) {
        t0 = __ldcs(nz0 + 2496 + lane);
        t1 = __ldcs(nz1 + 2496 + lane);
        t2 = __ldcs(nz2 + 2496 + lane);
        t3 = __ldcs(nz3 + 2496 + lane);
    }

    // epilogue: consume j=75,76,77 (already in buffers), no reloads
    #pragma unroll
    for (int k = 0; k < DEPTH; k++) {
        const int idx = (75 + k) * 32 + lane;
        float4 t = st4[idx], yv = sy4[idx];
        consume1(P0[k], t, yv, q0, q0s, q0y);
        consume1(P1[k], t, yv, q1, q1s, q1y);
        consume1(P2[k], t, yv, q2, q2s, q2y);
        consume1(P3[k], t, yv, q3, q3s, q3y);
    }
    if (lane < 4) {
        const int idx = 2496 + lane;
        float4 t = st4[idx], yv = sy4[idx];
        consume1(t0, t, yv, q0, q0s, q0y);
        consume1(t1, t, yv, q1, q1s, q1y);
        consume1(t2, t, yv, q2, q2s, q2y);
        consume1(t3, t, yv, q3, q3s, q3y);
    }

    // warp-local reductions for all four samples
    #pragma unroll
    for (int o = 16; o; o >>= 1) {
        q0 += __shfl_xor_sync(0xffffffffu, q0, o);
        q0s += __shfl_xor_sync(0xffffffffu, q0s, o);
        q0y += __shfl_xor_sync(0xffffffffu, q0y, o);
        q1 += __shfl_xor_sync(0xffffffffu, q1, o);
        q1s += __shfl_xor_sync(0xffffffffu, q1s, o);
        q1y += __shfl_xor_sync(0xffffffffu, q1y, o);
        q2 += __shfl_xor_sync(0xffffffffu, q2, o);
        q2s += __shfl_xor_sync(0xffffffffu, q2s, o);
        q2y += __shfl_xor_sync(0xffffffffu, q2y, o);
        q3 += __shfl_xor_sync(0xffffffffu, q3, o);
        q3s += __shfl_xor_sync(0xffffffffu, q3s, o);
        q3y += __shfl_xor_sync(0xffffffffu, q3y, o);
    }
    const float i0 = __frcp_rn(q0);
    const float i1 = __frcp_rn(q1);
    const float i2 = __frcp_rn(q2);
    const float i3 = __frcp_rn(q3);
    float acc = fmaf(i0 * i0, q0s, fmaf(-2.0f * i0, q0y, sy2))
              + fmaf(i1 * i1, q1s, fmaf(-2.0f * i1, q1y, sy2))
              + fmaf(i2 * i2, q2s, fmaf(-2.0f * i2, q2y, sy2))
              + fmaf(i3 * i3, q3s, fmaf(-2.0f * i3, q3y, sy2));

    // ---- block combine (single barrier) + fused grid reduction ----
    if (lane == 0) fin[warp] = acc;
    __syncthreads();
    if (tid == 0) {
        float tot = fin[0];
        #pragma unroll
        for (int w = 1; w < NWARPS; w++) tot += fin[w];
        g_partial[b] = tot;
        __threadfence();
        unsigned t = atomicAdd(&g_ticket, 1u);
        is_last = (t == B_DIM - 1) ? 1 : 0;
    }
    __syncthreads();

    if (is_last) {
        if (tid < B_DIM) {                     // warps 0..3
            float v = __ldcg(&g_partial[tid]);
            #pragma unroll
            for (int o = 16; o; o >>= 1) v += __shfl_xor_sync(0xffffffffu, v, o);
            if (lane == 0) fin[warp] = v;
        }
        __syncthreads();
        if (tid == 0) {
            float tot = fin[0] + fin[1] + fin[2] + fin[3];
            out[0] = tot * (1.0f / ((float)S_DIM * (float)B_DIM * (float)D_DIM));
            g_ticket = 0u;                      // reset for next graph replay
        }
    }
}

extern "C" void kernel_launch(void* const* d_in, const int* in_sizes, int n_in,
                              void* d_out, int out_size)
{
    const float* theta = (const float*)d_in[0];  // [B, D]
    const float* y     = (const float*)d_in[1];  // [B, D]
    const float* noise = (const float*)d_in[2];  // [S, B, D]
    float* out = (float*)d_out;

    cudaFuncSetAttribute(pl_fused,
                         cudaFuncAttributeMaxDynamicSharedMemorySize,
                         SMEM_BYTES);
    pl_fused<<<B_DIM, THREADS, SMEM_BYTES>>>(theta, y, noise, out);
}